// round 1
// baseline (speedup 1.0000x reference)
#include <cuda_runtime.h>
#include <math.h>

#define NSEQ 4096
#define BATCH 2
#define BN (BATCH*NSEQ)
#define FDIM 512
#define DDIM 64

// ---------------- scratch (device globals; no allocation allowed) ----------------
__device__ float g_Q[(size_t)BN*DDIM];
__device__ float g_K[(size_t)BN*DDIM];
__device__ float g_C[(size_t)BATCH*NSEQ*NSEQ];   // 128MB, only lower-tri tiles written
__device__ float g_ch[5][BN];                    // charge history: [0]=initial, [1..4]=after updates
__device__ float g_rm[BN];                       // row max of current L_t
__device__ float g_irs[BN];                      // 1/rowsum
__device__ float g_recv[BN];                     // column sums (received)

__device__ __forceinline__ float sigmoidf_(float x){ return 1.f/(1.f+__expf(-x)); }

// ---------------- Q/K projection + RoPE ----------------
// block: 16 rows, 256 threads (d = tid&63, row-group = tid>>6)
__global__ void qk_rope_kernel(const float* __restrict__ feat,
                               const float* __restrict__ cosb,
                               const float* __restrict__ sinb,
                               const float* __restrict__ Wq,
                               const float* __restrict__ Wk)
{
    __shared__ float fs[16][64];
    __shared__ float qs[16][64];
    __shared__ float ks[16][64];
    int tid = threadIdx.x;
    int d = tid & 63, rg = tid >> 6;
    long rowbase = (long)blockIdx.x * 16;
    float accq[4] = {0,0,0,0}, acck[4] = {0,0,0,0};
    for (int f0 = 0; f0 < FDIM; f0 += 64){
        __syncthreads();
        for (int i = tid; i < 16*64; i += 256){
            int r = i >> 6, f = i & 63;
            fs[r][f] = feat[(rowbase + r)*FDIM + f0 + f];
        }
        __syncthreads();
        #pragma unroll 8
        for (int f = 0; f < 64; f++){
            float wq = Wq[(f0+f)*DDIM + d];
            float wk = Wk[(f0+f)*DDIM + d];
            #pragma unroll
            for (int i = 0; i < 4; i++){
                float fv = fs[rg*4+i][f];
                accq[i] = fmaf(fv, wq, accq[i]);
                acck[i] = fmaf(fv, wk, acck[i]);
            }
        }
    }
    __syncthreads();
    #pragma unroll
    for (int i = 0; i < 4; i++){ qs[rg*4+i][d] = accq[i]; ks[rg*4+i][d] = acck[i]; }
    __syncthreads();
    #pragma unroll
    for (int i = 0; i < 4; i++){
        int r = rg*4+i;
        long n = rowbase + r;
        int nn = (int)(n & (NSEQ-1));
        float c = cosb[nn*DDIM+d], s = sinb[nn*DDIM+d];
        float q = qs[r][d], k = ks[r][d];
        float qr = (d < 32) ? -qs[r][d+32] : qs[r][d-32];
        float kr = (d < 32) ? -ks[r][d+32] : ks[r][d-32];
        g_Q[n*DDIM+d] = q*c + qr*s;
        g_K[n*DDIM+d] = k*c + kr*s;
    }
}

// ---------------- initial charge + zero recv ----------------
__global__ void charge0_kernel(const float* __restrict__ feat,
                               const float* __restrict__ cw,
                               const float* __restrict__ cb)
{
    int warp = threadIdx.x >> 5, lane = threadIdx.x & 31;
    long n = (long)blockIdx.x*8 + warp;
    if (n >= BN) return;
    float sum = 0.f;
    for (int f = lane; f < FDIM; f += 32) sum = fmaf(feat[n*FDIM+f], cw[f], sum);
    #pragma unroll
    for (int o = 16; o > 0; o >>= 1) sum += __shfl_down_sync(0xffffffffu, sum, o);
    if (lane == 0){
        g_ch[0][n] = sigmoidf_(sum + cb[0]);
        g_recv[n] = 0.f;
    }
}

// ---------------- C = Q K^T / 8, lower-triangular 64x64 tiles ----------------
__global__ void gemm2_kernel()
{
    int b = blockIdx.y;
    int k = blockIdx.x;
    int ti = (int)((sqrtf(8.f*(float)k + 1.f) - 1.f) * 0.5f);
    while ((ti+1)*(ti+2)/2 <= k) ti++;
    while (ti*(ti+1)/2 > k) ti--;
    int tj = k - ti*(ti+1)/2;

    __shared__ float Qs[64][65];
    __shared__ float Ks[64][65];
    const float* Qb = g_Q + ((long)b*NSEQ + ti*64)*DDIM;
    const float* Kb = g_K + ((long)b*NSEQ + tj*64)*DDIM;
    int tid = threadIdx.x;
    for (int i = tid; i < 64*64; i += 256){
        int r = i >> 6, c = i & 63;
        Qs[r][c] = Qb[i];
        Ks[r][c] = Kb[i];
    }
    __syncthreads();
    int tx = tid & 15, ty = tid >> 4;
    int i0 = ty*4, j0 = tx*4;
    float acc[4][4] = {};
    #pragma unroll 8
    for (int kk = 0; kk < 64; kk++){
        float a[4], bb[4];
        #pragma unroll
        for (int i = 0; i < 4; i++) a[i] = Qs[i0+i][kk];
        #pragma unroll
        for (int j = 0; j < 4; j++) bb[j] = Ks[j0+j][kk];
        #pragma unroll
        for (int i = 0; i < 4; i++)
            #pragma unroll
            for (int j = 0; j < 4; j++)
                acc[i][j] = fmaf(a[i], bb[j], acc[i][j]);
    }
    float* Cb = g_C + (size_t)b*NSEQ*NSEQ;
    #pragma unroll
    for (int i = 0; i < 4; i++){
        long row = (long)ti*64 + i0 + i;
        float4 v = make_float4(acc[i][0]*0.125f, acc[i][1]*0.125f,
                               acc[i][2]*0.125f, acc[i][3]*0.125f);
        *(float4*)&Cb[row*NSEQ + tj*64 + j0] = v;
    }
}

// ---------------- row max / row sumexp of L_t (block per row) ----------------
__global__ void rowstats_kernel(int t, const float* __restrict__ ssp)
{
    int blk = blockIdx.x;
    int b = blk >> 12;
    int n = (NSEQ-1) - (blk & (NSEQ-1));     // long rows first
    const float* Crow = g_C + ((size_t)b*NSEQ + n)*NSEQ;
    float ss = *ssp;
    float chn[4];
    #pragma unroll
    for (int u = 0; u < 4; u++) chn[u] = (u < t) ? ss*g_ch[u+1][b*NSEQ+n] : 0.f;

    int tid = threadIdx.x;
    float mx = -__int_as_float(0x7f800000);  // -inf
    float sm = 0.f;
    for (int m = tid; m <= n; m += 256){
        float fac = 1.f;
        #pragma unroll
        for (int u = 0; u < 4; u++)
            if (u < t) fac = fmaf(chn[u], g_ch[u+1][b*NSEQ+m], fac);
        float x = Crow[m]*fac;
        if (x > mx){ sm = sm*__expf(mx - x) + 1.f; mx = x; }
        else        sm += __expf(x - mx);
    }
    __shared__ float sM[256], sS[256];
    sM[tid] = mx; sS[tid] = sm;
    __syncthreads();
    for (int o = 128; o > 0; o >>= 1){
        if (tid < o){
            float m1 = sM[tid], s1 = sS[tid];
            float m2 = sM[tid+o], s2 = sS[tid+o];
            float M = fmaxf(m1, m2);
            float s = 0.f;
            if (s1 > 0.f) s += s1*__expf(m1 - M);
            if (s2 > 0.f) s += s2*__expf(m2 - M);
            sM[tid] = M; sS[tid] = s;
        }
        __syncthreads();
    }
    if (tid == 0){
        g_rm[b*NSEQ+n]  = sM[0];
        g_irs[b*NSEQ+n] = 1.f / sS[0];
    }
}

// ---------------- received (column sums of softmax) ----------------
// grid: x = col tiles (128 wide), y = row chunks (512), z = batch
__global__ void received_kernel(int t, const float* __restrict__ ssp)
{
    int b  = blockIdx.z;
    int m0 = blockIdx.x * 128;
    int r0 = blockIdx.y * 512;
    if (r0 + 512 <= m0) return;               // chunk entirely above diagonal
    int tid = threadIdx.x;
    int c  = tid & 127;
    int rp = tid >> 7;
    int m  = m0 + c;
    float ss = *ssp;
    float chm[4];
    #pragma unroll
    for (int u = 0; u < 4; u++) chm[u] = (u < t) ? ss*g_ch[u+1][b*NSEQ+m] : 0.f;

    float acc = 0.f;
    int nstart = (r0 > m0 ? r0 : m0) + rp;
    int nend   = (r0 + 512 < NSEQ) ? r0 + 512 : NSEQ;
    for (int n = nstart; n < nend; n += 2){
        if (m <= n){
            float fac = 1.f;
            #pragma unroll
            for (int u = 0; u < 4; u++)
                if (u < t) fac = fmaf(chm[u], g_ch[u+1][b*NSEQ+n], fac);
            float x = g_C[((size_t)b*NSEQ + n)*NSEQ + m] * fac;
            acc += __expf(x - g_rm[b*NSEQ+n]) * g_irs[b*NSEQ+n];
        }
    }
    __shared__ float s[256];
    s[tid] = acc;
    __syncthreads();
    if (tid < 128) atomicAdd(&g_recv[b*NSEQ + m0 + tid], s[tid] + s[tid+128]);
}

// ---------------- charge update (and re-zero recv) ----------------
__global__ void chargeupd_kernel(int t, const float* __restrict__ cdp)
{
    int i = blockIdx.x*256 + threadIdx.x;
    if (i >= BN) return;
    float cd = *cdp;
    float r  = g_recv[i];
    float sg = sigmoidf_(r - 1.f);
    g_ch[t+1][i] = g_ch[t][i] * (1.f - cd*sg);
    g_recv[i] = 0.f;
}

// ---------------- final softmax, full matrix (zeros above diagonal) ----------------
__global__ void final_kernel(float* __restrict__ out, const float* __restrict__ ssp)
{
    int blk = blockIdx.x;
    int b = blk >> 12;
    int n = blk & (NSEQ-1);
    size_t base = ((size_t)b*NSEQ + n)*NSEQ;
    float rm  = g_rm[b*NSEQ+n];
    float irs = g_irs[b*NSEQ+n];
    float ss  = *ssp;
    float chn[4];
    #pragma unroll
    for (int u = 0; u < 4; u++) chn[u] = ss*g_ch[u+1][b*NSEQ+n];

    int tid = threadIdx.x;
    for (int m4 = tid; m4 < NSEQ/4; m4 += 256){
        int m = m4*4;
        float4 o = make_float4(0.f, 0.f, 0.f, 0.f);
        if (m <= n){
            float vals[4];
            #pragma unroll
            for (int j = 0; j < 4; j++){
                int mm = m + j;
                float v = 0.f;
                if (mm <= n){
                    float fac = 1.f;
                    #pragma unroll
                    for (int u = 0; u < 4; u++)
                        fac = fmaf(chn[u], g_ch[u+1][b*NSEQ+mm], fac);
                    v = __expf(g_C[base+mm]*fac - rm) * irs;
                }
                vals[j] = v;
            }
            o = make_float4(vals[0], vals[1], vals[2], vals[3]);
        }
        *(float4*)&out[base + m] = o;
    }
}

// ---------------- launch ----------------
extern "C" void kernel_launch(void* const* d_in, const int* in_sizes, int n_in,
                              void* d_out, int out_size)
{
    const float* feat = (const float*)d_in[0];
    const float* cosb = (const float*)d_in[1];
    const float* sinb = (const float*)d_in[2];
    // d_in[3] = mask (causal; not needed)
    const float* Wq   = (const float*)d_in[4];
    const float* Wk   = (const float*)d_in[5];
    const float* cw   = (const float*)d_in[6];
    const float* cb   = (const float*)d_in[7];
    const float* ssp  = (const float*)d_in[8];
    const float* cdp  = (const float*)d_in[9];
    float* out = (float*)d_out;

    qk_rope_kernel<<<BN/16, 256>>>(feat, cosb, sinb, Wq, Wk);
    charge0_kernel<<<BN/8, 256>>>(feat, cw, cb);

    const int T = NSEQ/64;                      // 64 tiles per dim
    dim3 g2(T*(T+1)/2, BATCH);
    gemm2_kernel<<<g2, 256>>>();

    dim3 grv(NSEQ/128, NSEQ/512, BATCH);
    for (int t = 0; t < 4; t++){
        rowstats_kernel<<<BN, 256>>>(t, ssp);
        received_kernel<<<grv, 256>>>(t, ssp);
        chargeupd_kernel<<<BN/256, 256>>>(t, cdp);
    }
    rowstats_kernel<<<BN, 256>>>(4, ssp);
    final_kernel<<<BN, 256>>>(out, ssp);
}

// round 2
// speedup vs baseline: 1.3823x; 1.3823x over previous
#include <cuda_runtime.h>
#include <math.h>

#define NSEQ 4096
#define BATCH 2
#define BN (BATCH*NSEQ)
#define FDIM 512
#define DDIM 64

// ---------------- scratch (device globals; no allocation allowed) ----------------
__device__ float g_Q[(size_t)BN*DDIM];
__device__ float g_K[(size_t)BN*DDIM];
__device__ float g_C[(size_t)BATCH*NSEQ*NSEQ];   // 128MB, only lower-tri written (rest stays 0)
__device__ float g_ch[BN];                       // current charge
__device__ float g_chp[(size_t)BN*4];            // packed sqrt(ss)*charge history (components 0..3)
__device__ float g_irs[BN];                      // 1/rowsum
__device__ float g_recv[BN];                     // column sums (received)

__device__ __forceinline__ float sigmoidf_(float x){ return 1.f/(1.f+__expf(-x)); }

// ---------------- Q/K projection + RoPE ----------------
__global__ void qk_rope_kernel(const float* __restrict__ feat,
                               const float* __restrict__ cosb,
                               const float* __restrict__ sinb,
                               const float* __restrict__ Wq,
                               const float* __restrict__ Wk)
{
    __shared__ float fs[16][64];
    __shared__ float qs[16][64];
    __shared__ float ks[16][64];
    int tid = threadIdx.x;
    int d = tid & 63, rg = tid >> 6;
    long rowbase = (long)blockIdx.x * 16;
    float accq[4] = {0,0,0,0}, acck[4] = {0,0,0,0};
    for (int f0 = 0; f0 < FDIM; f0 += 64){
        __syncthreads();
        for (int i = tid; i < 16*64; i += 256){
            int r = i >> 6, f = i & 63;
            fs[r][f] = feat[(rowbase + r)*FDIM + f0 + f];
        }
        __syncthreads();
        #pragma unroll 8
        for (int f = 0; f < 64; f++){
            float wq = Wq[(f0+f)*DDIM + d];
            float wk = Wk[(f0+f)*DDIM + d];
            #pragma unroll
            for (int i = 0; i < 4; i++){
                float fv = fs[rg*4+i][f];
                accq[i] = fmaf(fv, wq, accq[i]);
                acck[i] = fmaf(fv, wk, acck[i]);
            }
        }
    }
    __syncthreads();
    #pragma unroll
    for (int i = 0; i < 4; i++){ qs[rg*4+i][d] = accq[i]; ks[rg*4+i][d] = acck[i]; }
    __syncthreads();
    #pragma unroll
    for (int i = 0; i < 4; i++){
        int r = rg*4+i;
        long n = rowbase + r;
        int nn = (int)(n & (NSEQ-1));
        float c = cosb[nn*DDIM+d], s = sinb[nn*DDIM+d];
        float q = qs[r][d], k = ks[r][d];
        float qr = (d < 32) ? -qs[r][d+32] : qs[r][d-32];
        float kr = (d < 32) ? -ks[r][d+32] : ks[r][d-32];
        g_Q[n*DDIM+d] = q*c + qr*s;
        g_K[n*DDIM+d] = k*c + kr*s;
    }
}

// ---------------- initial charge + zero recv + zero chp ----------------
__global__ void charge0_kernel(const float* __restrict__ feat,
                               const float* __restrict__ cw,
                               const float* __restrict__ cb)
{
    int warp = threadIdx.x >> 5, lane = threadIdx.x & 31;
    long n = (long)blockIdx.x*8 + warp;
    if (n >= BN) return;
    float sum = 0.f;
    for (int f = lane; f < FDIM; f += 32) sum = fmaf(feat[n*FDIM+f], cw[f], sum);
    #pragma unroll
    for (int o = 16; o > 0; o >>= 1) sum += __shfl_down_sync(0xffffffffu, sum, o);
    if (lane == 0){
        g_ch[n] = sigmoidf_(sum + cb[0]);
        g_recv[n] = 0.f;
        ((float4*)g_chp)[n] = make_float4(0.f, 0.f, 0.f, 0.f);
    }
}

// ---------------- C = Q K^T / 8, lower-triangular 64x64 tiles ----------------
__global__ void gemm2_kernel()
{
    int b = blockIdx.y;
    int k = blockIdx.x;
    int ti = (int)((sqrtf(8.f*(float)k + 1.f) - 1.f) * 0.5f);
    while ((ti+1)*(ti+2)/2 <= k) ti++;
    while (ti*(ti+1)/2 > k) ti--;
    int tj = k - ti*(ti+1)/2;

    __shared__ float Qs[64][65];
    __shared__ float Ks[64][65];
    const float* Qb = g_Q + ((long)b*NSEQ + ti*64)*DDIM;
    const float* Kb = g_K + ((long)b*NSEQ + tj*64)*DDIM;
    int tid = threadIdx.x;
    for (int i = tid; i < 64*64; i += 256){
        int r = i >> 6, c = i & 63;
        Qs[r][c] = Qb[i];
        Ks[r][c] = Kb[i];
    }
    __syncthreads();
    int tx = tid & 15, ty = tid >> 4;
    int i0 = ty*4, j0 = tx*4;
    float acc[4][4] = {};
    #pragma unroll 8
    for (int kk = 0; kk < 64; kk++){
        float a[4], bb[4];
        #pragma unroll
        for (int i = 0; i < 4; i++) a[i] = Qs[i0+i][kk];
        #pragma unroll
        for (int j = 0; j < 4; j++) bb[j] = Ks[j0+j][kk];
        #pragma unroll
        for (int i = 0; i < 4; i++)
            #pragma unroll
            for (int j = 0; j < 4; j++)
                acc[i][j] = fmaf(a[i], bb[j], acc[i][j]);
    }
    float* Cb = g_C + (size_t)b*NSEQ*NSEQ;
    #pragma unroll
    for (int i = 0; i < 4; i++){
        long row = (long)ti*64 + i0 + i;
        float4 v = make_float4(acc[i][0]*0.125f, acc[i][1]*0.125f,
                               acc[i][2]*0.125f, acc[i][3]*0.125f);
        *(float4*)&Cb[row*NSEQ + tj*64 + j0] = v;
    }
}

// ---------------- rowsum of exp(L_t): warp per row, branchless ----------------
__global__ void rowstats2_kernel()
{
    int gw   = blockIdx.x*8 + (threadIdx.x >> 5);
    int lane = threadIdx.x & 31;
    int b = gw & 1;
    int n = (NSEQ-1) - (gw >> 1);           // long rows first
    const float*  Crow = g_C + ((size_t)b*NSEQ + n)*NSEQ;
    const float4* chp  = ((const float4*)g_chp) + (size_t)b*NSEQ;
    float4 cn = chp[n];
    int L = n + 1;
    int nf4 = L >> 2;
    float sum = 0.f;
    for (int i = lane; i < nf4; i += 32){
        float4 c  = ((const float4*)Crow)[i];
        float4 q0 = chp[4*i+0], q1 = chp[4*i+1], q2 = chp[4*i+2], q3 = chp[4*i+3];
        float f0 = fmaf(cn.x,q0.x, fmaf(cn.y,q0.y, fmaf(cn.z,q0.z, fmaf(cn.w,q0.w, 1.f))));
        float f1 = fmaf(cn.x,q1.x, fmaf(cn.y,q1.y, fmaf(cn.z,q1.z, fmaf(cn.w,q1.w, 1.f))));
        float f2 = fmaf(cn.x,q2.x, fmaf(cn.y,q2.y, fmaf(cn.z,q2.z, fmaf(cn.w,q2.w, 1.f))));
        float f3 = fmaf(cn.x,q3.x, fmaf(cn.y,q3.y, fmaf(cn.z,q3.z, fmaf(cn.w,q3.w, 1.f))));
        sum += __expf(c.x*f0) + __expf(c.y*f1) + __expf(c.z*f2) + __expf(c.w*f3);
    }
    for (int m = nf4*4 + lane; m < L; m += 32){
        float4 q = chp[m];
        float f = fmaf(cn.x,q.x, fmaf(cn.y,q.y, fmaf(cn.z,q.z, fmaf(cn.w,q.w, 1.f))));
        sum += __expf(Crow[m]*f);
    }
    #pragma unroll
    for (int o = 16; o > 0; o >>= 1) sum += __shfl_down_sync(0xffffffffu, sum, o);
    if (lane == 0) g_irs[b*NSEQ + n] = 1.f / sum;
}

// ---------------- received (column sums of softmax) ----------------
// grid: x = 128-wide col tiles, y = 512-row chunks, z = batch; 256 thr
__global__ void received2_kernel()
{
    int b  = blockIdx.z;
    int m0 = blockIdx.x * 128;
    int r0 = blockIdx.y * 512;
    if (r0 + 512 <= m0) return;
    int tid = threadIdx.x;
    int c4  = tid & 31;                     // float4 slot within 128 cols
    int rp  = tid >> 5;                     // 8-way over rows
    int m   = m0 + c4*4;
    const float4* chp = ((const float4*)g_chp) + (size_t)b*NSEQ;
    float4 q0 = chp[m+0], q1 = chp[m+1], q2 = chp[m+2], q3 = chp[m+3];
    float4 acc = make_float4(0.f,0.f,0.f,0.f);
    int nstart = (r0 > m0 ? r0 : m0) + rp;
    int nend   = (r0 + 512 < NSEQ) ? r0 + 512 : NSEQ;
    for (int n = nstart; n < nend; n += 8){
        float4 cn = chp[n];
        float irs = g_irs[b*NSEQ + n];
        float4 cc = *(const float4*)&g_C[((size_t)b*NSEQ + n)*NSEQ + m];
        if (m + 3 <= n){
            float f0 = fmaf(cn.x,q0.x, fmaf(cn.y,q0.y, fmaf(cn.z,q0.z, fmaf(cn.w,q0.w, 1.f))));
            float f1 = fmaf(cn.x,q1.x, fmaf(cn.y,q1.y, fmaf(cn.z,q1.z, fmaf(cn.w,q1.w, 1.f))));
            float f2 = fmaf(cn.x,q2.x, fmaf(cn.y,q2.y, fmaf(cn.z,q2.z, fmaf(cn.w,q2.w, 1.f))));
            float f3 = fmaf(cn.x,q3.x, fmaf(cn.y,q3.y, fmaf(cn.z,q3.z, fmaf(cn.w,q3.w, 1.f))));
            acc.x += __expf(cc.x*f0)*irs;
            acc.y += __expf(cc.y*f1)*irs;
            acc.z += __expf(cc.z*f2)*irs;
            acc.w += __expf(cc.w*f3)*irs;
        } else {
            if (m+0 <= n){ float f = fmaf(cn.x,q0.x, fmaf(cn.y,q0.y, fmaf(cn.z,q0.z, fmaf(cn.w,q0.w, 1.f)))); acc.x += __expf(cc.x*f)*irs; }
            if (m+1 <= n){ float f = fmaf(cn.x,q1.x, fmaf(cn.y,q1.y, fmaf(cn.z,q1.z, fmaf(cn.w,q1.w, 1.f)))); acc.y += __expf(cc.y*f)*irs; }
            if (m+2 <= n){ float f = fmaf(cn.x,q2.x, fmaf(cn.y,q2.y, fmaf(cn.z,q2.z, fmaf(cn.w,q2.w, 1.f)))); acc.z += __expf(cc.z*f)*irs; }
        }
    }
    __shared__ float4 s4[256];
    s4[tid] = acc;
    __syncthreads();
    if (tid < 32){
        float4 t = s4[tid];
        #pragma unroll
        for (int r = 1; r < 8; r++){
            float4 o = s4[tid + r*32];
            t.x += o.x; t.y += o.y; t.z += o.z; t.w += o.w;
        }
        float* dst = &g_recv[b*NSEQ + m0 + tid*4];
        atomicAdd(dst+0, t.x);
        atomicAdd(dst+1, t.y);
        atomicAdd(dst+2, t.z);
        atomicAdd(dst+3, t.w);
    }
}

// ---------------- charge update + pack + re-zero recv ----------------
__global__ void chargeupd_kernel(int t, const float* __restrict__ cdp,
                                        const float* __restrict__ ssp)
{
    int i = blockIdx.x*256 + threadIdx.x;
    if (i >= BN) return;
    float cd = *cdp, ss = *ssp;
    float r  = g_recv[i];
    float ch = g_ch[i] * (1.f - cd*sigmoidf_(r - 1.f));
    g_ch[i] = ch;
    g_chp[(size_t)i*4 + t] = sqrtf(ss)*ch;
    g_recv[i] = 0.f;
}

// ---------------- final: fused rowsum + normalized softmax write ----------------
__global__ void final2_kernel(float* __restrict__ out)
{
    __shared__ float P[NSEQ];
    __shared__ float red[9];
    int blk = blockIdx.x;
    int b = blk & 1;
    int n = (NSEQ-1) - (blk >> 1);          // long rows first
    const float*  Crow = g_C + ((size_t)b*NSEQ + n)*NSEQ;
    const float4* chp  = ((const float4*)g_chp) + (size_t)b*NSEQ;
    float4 cn = chp[n];
    int tid = threadIdx.x, lane = tid & 31, wid = tid >> 5;
    int L = n + 1;
    int nf4 = L >> 2;
    float sum = 0.f;
    for (int i = tid; i < nf4; i += 256){
        float4 c  = ((const float4*)Crow)[i];
        float4 q0 = chp[4*i+0], q1 = chp[4*i+1], q2 = chp[4*i+2], q3 = chp[4*i+3];
        float f0 = fmaf(cn.x,q0.x, fmaf(cn.y,q0.y, fmaf(cn.z,q0.z, fmaf(cn.w,q0.w, 1.f))));
        float f1 = fmaf(cn.x,q1.x, fmaf(cn.y,q1.y, fmaf(cn.z,q1.z, fmaf(cn.w,q1.w, 1.f))));
        float f2 = fmaf(cn.x,q2.x, fmaf(cn.y,q2.y, fmaf(cn.z,q2.z, fmaf(cn.w,q2.w, 1.f))));
        float f3 = fmaf(cn.x,q3.x, fmaf(cn.y,q3.y, fmaf(cn.z,q3.z, fmaf(cn.w,q3.w, 1.f))));
        float p0 = __expf(c.x*f0), p1 = __expf(c.y*f1);
        float p2 = __expf(c.z*f2), p3 = __expf(c.w*f3);
        *(float4*)&P[4*i] = make_float4(p0,p1,p2,p3);
        sum += p0 + p1 + p2 + p3;
    }
    for (int m = nf4*4 + tid; m < L; m += 256){
        float4 q = chp[m];
        float f = fmaf(cn.x,q.x, fmaf(cn.y,q.y, fmaf(cn.z,q.z, fmaf(cn.w,q.w, 1.f))));
        float p = __expf(Crow[m]*f);
        P[m] = p;
        sum += p;
    }
    #pragma unroll
    for (int o = 16; o > 0; o >>= 1) sum += __shfl_down_sync(0xffffffffu, sum, o);
    if (lane == 0) red[wid] = sum;
    __syncthreads();
    if (tid == 0){
        float s = 0.f;
        #pragma unroll
        for (int w = 0; w < 8; w++) s += red[w];
        red[8] = 1.f / s;
    }
    __syncthreads();
    float irs = red[8];
    float* orow = out + ((size_t)b*NSEQ + n)*NSEQ;
    for (int i = tid; i < NSEQ/4; i += 256){
        int m = i*4;
        float4 v;
        if (m + 3 < L){
            float4 p = *(float4*)&P[m];
            v = make_float4(p.x*irs, p.y*irs, p.z*irs, p.w*irs);
        } else {
            v.x = (m+0 < L) ? P[m+0]*irs : 0.f;
            v.y = (m+1 < L) ? P[m+1]*irs : 0.f;
            v.z = (m+2 < L) ? P[m+2]*irs : 0.f;
            v.w = (m+3 < L) ? P[m+3]*irs : 0.f;
        }
        *(float4*)&orow[m] = v;
    }
}

// ---------------- launch ----------------
extern "C" void kernel_launch(void* const* d_in, const int* in_sizes, int n_in,
                              void* d_out, int out_size)
{
    const float* feat = (const float*)d_in[0];
    const float* cosb = (const float*)d_in[1];
    const float* sinb = (const float*)d_in[2];
    // d_in[3] = mask (causal; not needed)
    const float* Wq   = (const float*)d_in[4];
    const float* Wk   = (const float*)d_in[5];
    const float* cw   = (const float*)d_in[6];
    const float* cb   = (const float*)d_in[7];
    const float* ssp  = (const float*)d_in[8];
    const float* cdp  = (const float*)d_in[9];
    float* out = (float*)d_out;

    qk_rope_kernel<<<BN/16, 256>>>(feat, cosb, sinb, Wq, Wk);
    charge0_kernel<<<BN/8, 256>>>(feat, cw, cb);

    const int T = NSEQ/64;
    dim3 g2(T*(T+1)/2, BATCH);
    gemm2_kernel<<<g2, 256>>>();

    dim3 grv(NSEQ/128, NSEQ/512, BATCH);
    for (int t = 0; t < 4; t++){
        rowstats2_kernel<<<BN/8, 256>>>();
        received2_kernel<<<grv, 256>>>();
        chargeupd_kernel<<<BN/256, 256>>>(t, cdp, ssp);
    }
    final2_kernel<<<BN, 256>>>(out);
}

// round 3
// speedup vs baseline: 1.5368x; 1.1117x over previous
#include <cuda_runtime.h>
#include <math.h>

#define NSEQ 4096
#define BATCH 2
#define BN (BATCH*NSEQ)
#define FDIM 512
#define DDIM 64

// ---------------- scratch (device globals; no allocation allowed) ----------------
__device__ float g_Q[(size_t)BN*DDIM];
__device__ float g_K[(size_t)BN*DDIM];
__device__ float g_C[(size_t)BATCH*NSEQ*NSEQ];   // 128MB, lower-tri (+diag band) written
__device__ float g_ch[BN];                       // current charge
__device__ float g_chp[(size_t)BN*4];            // packed sqrt(ss)*charge history
__device__ float g_rs[BN];                       // rowsum accumulator
__device__ float g_irs[BN];                      // 1/rowsum
__device__ float g_recv[BN];                     // column sums (received)

__device__ __forceinline__ float sigmoidf_(float x){ return 1.f/(1.f+__expf(-x)); }

// ---------------- Q/K projection + RoPE ----------------
__global__ void qk_rope_kernel(const float* __restrict__ feat,
                               const float* __restrict__ cosb,
                               const float* __restrict__ sinb,
                               const float* __restrict__ Wq,
                               const float* __restrict__ Wk)
{
    __shared__ float fs[16][64];
    __shared__ float qs[16][64];
    __shared__ float ks[16][64];
    int tid = threadIdx.x;
    int d = tid & 63, rg = tid >> 6;
    long rowbase = (long)blockIdx.x * 16;
    float accq[4] = {0,0,0,0}, acck[4] = {0,0,0,0};
    for (int f0 = 0; f0 < FDIM; f0 += 64){
        __syncthreads();
        for (int i = tid; i < 16*64; i += 256){
            int r = i >> 6, f = i & 63;
            fs[r][f] = feat[(rowbase + r)*FDIM + f0 + f];
        }
        __syncthreads();
        #pragma unroll 8
        for (int f = 0; f < 64; f++){
            float wq = Wq[(f0+f)*DDIM + d];
            float wk = Wk[(f0+f)*DDIM + d];
            #pragma unroll
            for (int i = 0; i < 4; i++){
                float fv = fs[rg*4+i][f];
                accq[i] = fmaf(fv, wq, accq[i]);
                acck[i] = fmaf(fv, wk, acck[i]);
            }
        }
    }
    __syncthreads();
    #pragma unroll
    for (int i = 0; i < 4; i++){ qs[rg*4+i][d] = accq[i]; ks[rg*4+i][d] = acck[i]; }
    __syncthreads();
    #pragma unroll
    for (int i = 0; i < 4; i++){
        int r = rg*4+i;
        long n = rowbase + r;
        int nn = (int)(n & (NSEQ-1));
        float c = cosb[nn*DDIM+d], s = sinb[nn*DDIM+d];
        float q = qs[r][d], k = ks[r][d];
        float qr = (d < 32) ? -qs[r][d+32] : qs[r][d-32];
        float kr = (d < 32) ? -ks[r][d+32] : ks[r][d-32];
        g_Q[n*DDIM+d] = q*c + qr*s;
        g_K[n*DDIM+d] = k*c + kr*s;
    }
}

// ---------------- initial charge + zero recv/rs/chp ----------------
__global__ void charge0_kernel(const float* __restrict__ feat,
                               const float* __restrict__ cw,
                               const float* __restrict__ cb)
{
    int warp = threadIdx.x >> 5, lane = threadIdx.x & 31;
    long n = (long)blockIdx.x*8 + warp;
    if (n >= BN) return;
    float sum = 0.f;
    for (int f = lane; f < FDIM; f += 32) sum = fmaf(feat[n*FDIM+f], cw[f], sum);
    #pragma unroll
    for (int o = 16; o > 0; o >>= 1) sum += __shfl_down_sync(0xffffffffu, sum, o);
    if (lane == 0){
        g_ch[n] = sigmoidf_(sum + cb[0]);
        g_recv[n] = 0.f;
        g_rs[n] = 0.f;
        ((float4*)g_chp)[n] = make_float4(0.f, 0.f, 0.f, 0.f);
    }
}

// ---------------- C = Q K^T / 8, 128x128 lower-tri tiles ----------------
__global__ void __launch_bounds__(256, 2) gemm3_kernel()
{
    int b = blockIdx.y;
    int kidx = blockIdx.x;
    int ti = (int)((sqrtf(8.f*(float)kidx + 1.f) - 1.f) * 0.5f);
    while ((ti+1)*(ti+2)/2 <= kidx) ti++;
    while (ti*(ti+1)/2 > kidx) ti--;
    int tj = kidx - ti*(ti+1)/2;

    __shared__ float Qs[128][33];
    __shared__ float Ks[128][33];
    const float* Qb = g_Q + ((long)b*NSEQ + (long)ti*128)*DDIM;
    const float* Kb = g_K + ((long)b*NSEQ + (long)tj*128)*DDIM;
    int tid = threadIdx.x;
    int tx = tid & 15, ty = tid >> 4;
    float acc[8][8] = {};
    for (int k0 = 0; k0 < 64; k0 += 32){
        __syncthreads();
        for (int i = tid; i < 128*32; i += 256){
            int r = i >> 5, k = i & 31;
            Qs[r][k] = Qb[r*64 + k0 + k];
            Ks[r][k] = Kb[r*64 + k0 + k];
        }
        __syncthreads();
        #pragma unroll
        for (int kk = 0; kk < 32; kk++){
            float a[8], bb[8];
            #pragma unroll
            for (int i = 0; i < 8; i++) a[i]  = Qs[ty + i*16][kk];
            #pragma unroll
            for (int j = 0; j < 8; j++) bb[j] = Ks[tx + j*16][kk];
            #pragma unroll
            for (int i = 0; i < 8; i++)
                #pragma unroll
                for (int j = 0; j < 8; j++)
                    acc[i][j] = fmaf(a[i], bb[j], acc[i][j]);
        }
    }
    float* Cb = g_C + (size_t)b*NSEQ*NSEQ;
    #pragma unroll
    for (int i = 0; i < 8; i++){
        long row = (long)ti*128 + ty + i*16;
        #pragma unroll
        for (int j = 0; j < 8; j++){
            Cb[row*NSEQ + tj*128 + tx + j*16] = acc[i][j]*0.125f;
        }
    }
}

// ---------------- tiled rowsum: block = 128 cols x 256 rows ----------------
__global__ void rowsum_kernel()
{
    int b  = blockIdx.z;
    int m0 = blockIdx.x * 128;
    int n0 = blockIdx.y * 256;
    if (m0 > n0 + 255) return;
    int tid = threadIdx.x, lane = tid & 31, wid = tid >> 5;
    int m = m0 + lane*4;
    const float4* chp = ((const float4*)g_chp) + (size_t)b*NSEQ;
    float4 q0 = chp[m+0], q1 = chp[m+1], q2 = chp[m+2], q3 = chp[m+3];
    int nbase = n0 + wid*32;
    #pragma unroll 4
    for (int k = 0; k < 32; k++){
        int n = nbase + k;
        if (m0 > n) continue;
        float4 cn = chp[n];
        float4 cc = *(const float4*)&g_C[((size_t)b*NSEQ + n)*NSEQ + m];
        float f0 = fmaf(cn.x,q0.x, fmaf(cn.y,q0.y, fmaf(cn.z,q0.z, fmaf(cn.w,q0.w, 1.f))));
        float f1 = fmaf(cn.x,q1.x, fmaf(cn.y,q1.y, fmaf(cn.z,q1.z, fmaf(cn.w,q1.w, 1.f))));
        float f2 = fmaf(cn.x,q2.x, fmaf(cn.y,q2.y, fmaf(cn.z,q2.z, fmaf(cn.w,q2.w, 1.f))));
        float f3 = fmaf(cn.x,q3.x, fmaf(cn.y,q3.y, fmaf(cn.z,q3.z, fmaf(cn.w,q3.w, 1.f))));
        float s = ((m+0<=n)?__expf(cc.x*f0):0.f)
                + ((m+1<=n)?__expf(cc.y*f1):0.f)
                + ((m+2<=n)?__expf(cc.z*f2):0.f)
                + ((m+3<=n)?__expf(cc.w*f3):0.f);
        #pragma unroll
        for (int o = 16; o > 0; o >>= 1) s += __shfl_down_sync(0xffffffffu, s, o);
        if (lane == 0) atomicAdd(&g_rs[b*NSEQ + n], s);
    }
}

// ---------------- irs = 1/rs; zero rs ----------------
__global__ void invrs_kernel()
{
    int i = blockIdx.x*256 + threadIdx.x;
    if (i >= BN) return;
    g_irs[i] = 1.f / g_rs[i];
    g_rs[i] = 0.f;
}

// ---------------- tiled colsum (received): block = 128 cols x 256 rows ----------------
__global__ void colsum_kernel()
{
    int b  = blockIdx.z;
    int m0 = blockIdx.x * 128;
    int n0 = blockIdx.y * 256;
    if (m0 > n0 + 255) return;
    int tid = threadIdx.x, lane = tid & 31, wid = tid >> 5;
    int m = m0 + lane*4;
    const float4* chp = ((const float4*)g_chp) + (size_t)b*NSEQ;
    float4 q0 = chp[m+0], q1 = chp[m+1], q2 = chp[m+2], q3 = chp[m+3];
    float4 acc = make_float4(0.f,0.f,0.f,0.f);
    int nbase = n0 + wid*32;
    #pragma unroll 4
    for (int k = 0; k < 32; k++){
        int n = nbase + k;
        if (m0 > n) continue;
        float4 cn = chp[n];
        float irs = g_irs[b*NSEQ + n];
        float4 cc = *(const float4*)&g_C[((size_t)b*NSEQ + n)*NSEQ + m];
        float f0 = fmaf(cn.x,q0.x, fmaf(cn.y,q0.y, fmaf(cn.z,q0.z, fmaf(cn.w,q0.w, 1.f))));
        float f1 = fmaf(cn.x,q1.x, fmaf(cn.y,q1.y, fmaf(cn.z,q1.z, fmaf(cn.w,q1.w, 1.f))));
        float f2 = fmaf(cn.x,q2.x, fmaf(cn.y,q2.y, fmaf(cn.z,q2.z, fmaf(cn.w,q2.w, 1.f))));
        float f3 = fmaf(cn.x,q3.x, fmaf(cn.y,q3.y, fmaf(cn.z,q3.z, fmaf(cn.w,q3.w, 1.f))));
        acc.x += (m+0<=n) ? __expf(cc.x*f0)*irs : 0.f;
        acc.y += (m+1<=n) ? __expf(cc.y*f1)*irs : 0.f;
        acc.z += (m+2<=n) ? __expf(cc.z*f2)*irs : 0.f;
        acc.w += (m+3<=n) ? __expf(cc.w*f3)*irs : 0.f;
    }
    __shared__ float4 s4[256];
    s4[tid] = acc;
    __syncthreads();
    if (tid < 32){
        float4 t = s4[tid];
        #pragma unroll
        for (int r = 1; r < 8; r++){
            float4 o = s4[tid + r*32];
            t.x += o.x; t.y += o.y; t.z += o.z; t.w += o.w;
        }
        float* dst = &g_recv[b*NSEQ + m0 + tid*4];
        atomicAdd(dst+0, t.x);
        atomicAdd(dst+1, t.y);
        atomicAdd(dst+2, t.z);
        atomicAdd(dst+3, t.w);
    }
}

// ---------------- charge update + pack + re-zero recv ----------------
__global__ void chargeupd_kernel(int t, const float* __restrict__ cdp,
                                        const float* __restrict__ ssp)
{
    int i = blockIdx.x*256 + threadIdx.x;
    if (i >= BN) return;
    float cd = *cdp, ss = *ssp;
    float r  = g_recv[i];
    float ch = g_ch[i] * (1.f - cd*sigmoidf_(r - 1.f));
    g_ch[i] = ch;
    g_chp[(size_t)i*4 + t] = sqrtf(ss)*ch;
    g_recv[i] = 0.f;
}

// ---------------- tiled output: block = 128 cols x 128 rows ----------------
__global__ void output_kernel(float* __restrict__ out)
{
    int b  = blockIdx.z;
    int m0 = blockIdx.x * 128;
    int n0 = blockIdx.y * 128;
    int tid = threadIdx.x, lane = tid & 31, wid = tid >> 5;
    int m = m0 + lane*4;
    int nbase = n0 + wid*16;
    if (m0 > n0 + 127){
        // fully above diagonal: zeros, no C read
        float4 z = make_float4(0.f,0.f,0.f,0.f);
        #pragma unroll 4
        for (int k = 0; k < 16; k++){
            int n = nbase + k;
            *(float4*)&out[((size_t)b*NSEQ + n)*NSEQ + m] = z;
        }
        return;
    }
    const float4* chp = ((const float4*)g_chp) + (size_t)b*NSEQ;
    float4 q0 = chp[m+0], q1 = chp[m+1], q2 = chp[m+2], q3 = chp[m+3];
    #pragma unroll 2
    for (int k = 0; k < 16; k++){
        int n = nbase + k;
        float4 v = make_float4(0.f,0.f,0.f,0.f);
        if (m0 <= n){
            float4 cn = chp[n];
            float irs = g_irs[b*NSEQ + n];
            float4 cc = *(const float4*)&g_C[((size_t)b*NSEQ + n)*NSEQ + m];
            float f0 = fmaf(cn.x,q0.x, fmaf(cn.y,q0.y, fmaf(cn.z,q0.z, fmaf(cn.w,q0.w, 1.f))));
            float f1 = fmaf(cn.x,q1.x, fmaf(cn.y,q1.y, fmaf(cn.z,q1.z, fmaf(cn.w,q1.w, 1.f))));
            float f2 = fmaf(cn.x,q2.x, fmaf(cn.y,q2.y, fmaf(cn.z,q2.z, fmaf(cn.w,q2.w, 1.f))));
            float f3 = fmaf(cn.x,q3.x, fmaf(cn.y,q3.y, fmaf(cn.z,q3.z, fmaf(cn.w,q3.w, 1.f))));
            v.x = (m+0<=n) ? __expf(cc.x*f0)*irs : 0.f;
            v.y = (m+1<=n) ? __expf(cc.y*f1)*irs : 0.f;
            v.z = (m+2<=n) ? __expf(cc.z*f2)*irs : 0.f;
            v.w = (m+3<=n) ? __expf(cc.w*f3)*irs : 0.f;
        }
        *(float4*)&out[((size_t)b*NSEQ + n)*NSEQ + m] = v;
    }
}

// ---------------- launch ----------------
extern "C" void kernel_launch(void* const* d_in, const int* in_sizes, int n_in,
                              void* d_out, int out_size)
{
    const float* feat = (const float*)d_in[0];
    const float* cosb = (const float*)d_in[1];
    const float* sinb = (const float*)d_in[2];
    // d_in[3] = mask (causal; not needed)
    const float* Wq   = (const float*)d_in[4];
    const float* Wk   = (const float*)d_in[5];
    const float* cw   = (const float*)d_in[6];
    const float* cb   = (const float*)d_in[7];
    const float* ssp  = (const float*)d_in[8];
    const float* cdp  = (const float*)d_in[9];
    float* out = (float*)d_out;

    qk_rope_kernel<<<BN/16, 256>>>(feat, cosb, sinb, Wq, Wk);
    charge0_kernel<<<BN/8, 256>>>(feat, cw, cb);

    const int T = NSEQ/128;                      // 32 tiles per dim
    dim3 g3(T*(T+1)/2, BATCH);
    gemm3_kernel<<<g3, 256>>>();

    dim3 gpass(NSEQ/128, NSEQ/256, BATCH);
    for (int t = 0; t < 4; t++){
        rowsum_kernel<<<gpass, 256>>>();
        invrs_kernel<<<BN/256, 256>>>();
        colsum_kernel<<<gpass, 256>>>();
        chargeupd_kernel<<<BN/256, 256>>>(t, cdp, ssp);
    }
    rowsum_kernel<<<gpass, 256>>>();
    invrs_kernel<<<BN/256, 256>>>();
    dim3 gout(NSEQ/128, NSEQ/128, BATCH);
    output_kernel<<<gout, 256>>>(out);
}

// round 4
// speedup vs baseline: 1.5654x; 1.0186x over previous
#include <cuda_runtime.h>
#include <math.h>

#define NSEQ 4096
#define BATCH 2
#define BN (BATCH*NSEQ)
#define FDIM 512
#define DDIM 64

// ---------------- scratch (device globals; no allocation allowed) ----------------
__device__ float g_Q[(size_t)BN*DDIM];
__device__ float g_K[(size_t)BN*DDIM];
__device__ float g_C[(size_t)BATCH*NSEQ*NSEQ];   // 128MB, lower-tri written; rest stays 0
__device__ float g_ch[BN];                       // current charge
__device__ float g_chp[(size_t)BN*4];            // packed sqrt(ss)*charge history
__device__ float g_rs[BN];                       // rowsum accumulator
__device__ float g_recv[BN];                     // column sums (received)

__device__ __forceinline__ float sigmoidf_(float x){ return 1.f/(1.f+__expf(-x)); }

// ---------------- Q/K projection + RoPE ----------------
__global__ void qk_rope_kernel(const float* __restrict__ feat,
                               const float* __restrict__ cosb,
                               const float* __restrict__ sinb,
                               const float* __restrict__ Wq,
                               const float* __restrict__ Wk)
{
    __shared__ float fs[16][64];
    __shared__ float qs[16][64];
    __shared__ float ks[16][64];
    int tid = threadIdx.x;
    int d = tid & 63, rg = tid >> 6;
    long rowbase = (long)blockIdx.x * 16;
    float accq[4] = {0,0,0,0}, acck[4] = {0,0,0,0};
    for (int f0 = 0; f0 < FDIM; f0 += 64){
        __syncthreads();
        for (int i = tid; i < 16*64; i += 256){
            int r = i >> 6, f = i & 63;
            fs[r][f] = feat[(rowbase + r)*FDIM + f0 + f];
        }
        __syncthreads();
        #pragma unroll 8
        for (int f = 0; f < 64; f++){
            float wq = Wq[(f0+f)*DDIM + d];
            float wk = Wk[(f0+f)*DDIM + d];
            #pragma unroll
            for (int i = 0; i < 4; i++){
                float fv = fs[rg*4+i][f];
                accq[i] = fmaf(fv, wq, accq[i]);
                acck[i] = fmaf(fv, wk, acck[i]);
            }
        }
    }
    __syncthreads();
    #pragma unroll
    for (int i = 0; i < 4; i++){ qs[rg*4+i][d] = accq[i]; ks[rg*4+i][d] = acck[i]; }
    __syncthreads();
    #pragma unroll
    for (int i = 0; i < 4; i++){
        int r = rg*4+i;
        long n = rowbase + r;
        int nn = (int)(n & (NSEQ-1));
        float c = cosb[nn*DDIM+d], s = sinb[nn*DDIM+d];
        float q = qs[r][d], k = ks[r][d];
        float qr = (d < 32) ? -qs[r][d+32] : qs[r][d-32];
        float kr = (d < 32) ? -ks[r][d+32] : ks[r][d-32];
        g_Q[n*DDIM+d] = q*c + qr*s;
        g_K[n*DDIM+d] = k*c + kr*s;
    }
}

// ---------------- initial charge + zero recv/rs/chp ----------------
__global__ void charge0_kernel(const float* __restrict__ feat,
                               const float* __restrict__ cw,
                               const float* __restrict__ cb)
{
    int warp = threadIdx.x >> 5, lane = threadIdx.x & 31;
    long n = (long)blockIdx.x*8 + warp;
    if (n >= BN) return;
    float sum = 0.f;
    for (int f = lane; f < FDIM; f += 32) sum = fmaf(feat[n*FDIM+f], cw[f], sum);
    #pragma unroll
    for (int o = 16; o > 0; o >>= 1) sum += __shfl_down_sync(0xffffffffu, sum, o);
    if (lane == 0){
        g_ch[n] = sigmoidf_(sum + cb[0]);
        g_recv[n] = 0.f;
        g_rs[n] = 0.f;
        ((float4*)g_chp)[n] = make_float4(0.f, 0.f, 0.f, 0.f);
    }
}

// ---------------- C = Q K^T / 8, 128x128 lower-tri tiles ----------------
__global__ void __launch_bounds__(256, 2) gemm3_kernel()
{
    int b = blockIdx.y;
    int kidx = blockIdx.x;
    int ti = (int)((sqrtf(8.f*(float)kidx + 1.f) - 1.f) * 0.5f);
    while ((ti+1)*(ti+2)/2 <= kidx) ti++;
    while (ti*(ti+1)/2 > kidx) ti--;
    int tj = kidx - ti*(ti+1)/2;

    __shared__ float Qs[128][33];
    __shared__ float Ks[128][33];
    const float* Qb = g_Q + ((long)b*NSEQ + (long)ti*128)*DDIM;
    const float* Kb = g_K + ((long)b*NSEQ + (long)tj*128)*DDIM;
    int tid = threadIdx.x;
    int tx = tid & 15, ty = tid >> 4;
    float acc[8][8] = {};
    for (int k0 = 0; k0 < 64; k0 += 32){
        __syncthreads();
        for (int i = tid; i < 128*32; i += 256){
            int r = i >> 5, k = i & 31;
            Qs[r][k] = Qb[r*64 + k0 + k];
            Ks[r][k] = Kb[r*64 + k0 + k];
        }
        __syncthreads();
        #pragma unroll
        for (int kk = 0; kk < 32; kk++){
            float a[8], bb[8];
            #pragma unroll
            for (int i = 0; i < 8; i++) a[i]  = Qs[ty + i*16][kk];
            #pragma unroll
            for (int j = 0; j < 8; j++) bb[j] = Ks[tx + j*16][kk];
            #pragma unroll
            for (int i = 0; i < 8; i++)
                #pragma unroll
                for (int j = 0; j < 8; j++)
                    acc[i][j] = fmaf(a[i], bb[j], acc[i][j]);
        }
    }
    float* Cb = g_C + (size_t)b*NSEQ*NSEQ;
    #pragma unroll
    for (int i = 0; i < 8; i++){
        long row = (long)ti*128 + ty + i*16;
        #pragma unroll
        for (int j = 0; j < 8; j++){
            Cb[row*NSEQ + tj*128 + tx + j*16] = acc[i][j]*0.125f;
        }
    }
}

// ---------------- rowsum v2: warp = 8 rows x 512 cols, register acc ----------------
__global__ void __launch_bounds__(256) rowsum_kernel()
{
    int b  = blockIdx.z;
    int m0 = blockIdx.x * 512;
    int n0 = blockIdx.y * 64;
    if (m0 > n0 + 63) return;
    int lane = threadIdx.x & 31, wid = threadIdx.x >> 5;
    int nr0 = n0 + wid*8;
    const float4* chp = ((const float4*)g_chp) + (size_t)b*NSEQ;
    const float* Cb = g_C + (size_t)b*NSEQ*NSEQ;
    float acc[8] = {0.f,0.f,0.f,0.f,0.f,0.f,0.f,0.f};
    #pragma unroll
    for (int i = 0; i < 4; i++){
        int mchunk = m0 + i*128;
        if (mchunk > nr0 + 7) break;
        int m = mchunk + lane*4;
        float4 q0 = chp[m+0], q1 = chp[m+1], q2 = chp[m+2], q3 = chp[m+3];
        #pragma unroll
        for (int r = 0; r < 8; r++){
            int n = nr0 + r;
            if (mchunk > n) continue;
            float4 cn = chp[n];
            float4 cc = *(const float4*)&Cb[(size_t)n*NSEQ + m];
            float f0 = fmaf(cn.x,q0.x, fmaf(cn.y,q0.y, fmaf(cn.z,q0.z, fmaf(cn.w,q0.w, 1.f))));
            float f1 = fmaf(cn.x,q1.x, fmaf(cn.y,q1.y, fmaf(cn.z,q1.z, fmaf(cn.w,q1.w, 1.f))));
            float f2 = fmaf(cn.x,q2.x, fmaf(cn.y,q2.y, fmaf(cn.z,q2.z, fmaf(cn.w,q2.w, 1.f))));
            float f3 = fmaf(cn.x,q3.x, fmaf(cn.y,q3.y, fmaf(cn.z,q3.z, fmaf(cn.w,q3.w, 1.f))));
            float e0 = (m+0<=n) ? __expf(cc.x*f0) : 0.f;
            float e1 = (m+1<=n) ? __expf(cc.y*f1) : 0.f;
            float e2 = (m+2<=n) ? __expf(cc.z*f2) : 0.f;
            float e3 = (m+3<=n) ? __expf(cc.w*f3) : 0.f;
            acc[r] += (e0 + e1) + (e2 + e3);
        }
    }
    #pragma unroll
    for (int r = 0; r < 8; r++){
        float s = acc[r];
        #pragma unroll
        for (int o = 16; o > 0; o >>= 1) s += __shfl_down_sync(0xffffffffu, s, o);
        if (lane == 0 && s != 0.f) atomicAdd(&g_rs[b*NSEQ + nr0 + r], s);
    }
}

// ---------------- tiled colsum (received): block = 128 cols x 256 rows ----------------
__global__ void colsum_kernel()
{
    int b  = blockIdx.z;
    int m0 = blockIdx.x * 128;
    int n0 = blockIdx.y * 256;
    if (m0 > n0 + 255) return;
    int tid = threadIdx.x, lane = tid & 31, wid = tid >> 5;
    int m = m0 + lane*4;
    const float4* chp = ((const float4*)g_chp) + (size_t)b*NSEQ;
    float4 q0 = chp[m+0], q1 = chp[m+1], q2 = chp[m+2], q3 = chp[m+3];
    float4 acc = make_float4(0.f,0.f,0.f,0.f);
    int nbase = n0 + wid*32;
    #pragma unroll 4
    for (int k = 0; k < 32; k++){
        int n = nbase + k;
        if (m0 > n) continue;
        float4 cn = chp[n];
        float irs = __frcp_rn(g_rs[b*NSEQ + n]);
        float4 cc = *(const float4*)&g_C[((size_t)b*NSEQ + n)*NSEQ + m];
        float f0 = fmaf(cn.x,q0.x, fmaf(cn.y,q0.y, fmaf(cn.z,q0.z, fmaf(cn.w,q0.w, 1.f))));
        float f1 = fmaf(cn.x,q1.x, fmaf(cn.y,q1.y, fmaf(cn.z,q1.z, fmaf(cn.w,q1.w, 1.f))));
        float f2 = fmaf(cn.x,q2.x, fmaf(cn.y,q2.y, fmaf(cn.z,q2.z, fmaf(cn.w,q2.w, 1.f))));
        float f3 = fmaf(cn.x,q3.x, fmaf(cn.y,q3.y, fmaf(cn.z,q3.z, fmaf(cn.w,q3.w, 1.f))));
        acc.x += (m+0<=n) ? __expf(cc.x*f0)*irs : 0.f;
        acc.y += (m+1<=n) ? __expf(cc.y*f1)*irs : 0.f;
        acc.z += (m+2<=n) ? __expf(cc.z*f2)*irs : 0.f;
        acc.w += (m+3<=n) ? __expf(cc.w*f3)*irs : 0.f;
    }
    __shared__ float4 s4[256];
    s4[tid] = acc;
    __syncthreads();
    if (tid < 32){
        float4 t = s4[tid];
        #pragma unroll
        for (int r = 1; r < 8; r++){
            float4 o = s4[tid + r*32];
            t.x += o.x; t.y += o.y; t.z += o.z; t.w += o.w;
        }
        float* dst = &g_recv[b*NSEQ + m0 + tid*4];
        atomicAdd(dst+0, t.x);
        atomicAdd(dst+1, t.y);
        atomicAdd(dst+2, t.z);
        atomicAdd(dst+3, t.w);
    }
}

// ---------------- charge update + pack + re-zero recv/rs ----------------
__global__ void chargeupd_kernel(int t, const float* __restrict__ cdp,
                                        const float* __restrict__ ssp)
{
    int i = blockIdx.x*256 + threadIdx.x;
    if (i >= BN) return;
    float cd = *cdp, ss = *ssp;
    float r  = g_recv[i];
    float ch = g_ch[i] * (1.f - cd*sigmoidf_(r - 1.f));
    g_ch[i] = ch;
    g_chp[(size_t)i*4 + t] = sqrtf(ss)*ch;
    g_recv[i] = 0.f;
    g_rs[i] = 0.f;
}

// ---------------- tiled output: block = 128 cols x 128 rows ----------------
__global__ void output_kernel(float* __restrict__ out)
{
    int b  = blockIdx.z;
    int m0 = blockIdx.x * 128;
    int n0 = blockIdx.y * 128;
    int tid = threadIdx.x, lane = tid & 31, wid = tid >> 5;
    int m = m0 + lane*4;
    int nbase = n0 + wid*16;
    if (m0 > n0 + 127){
        float4 z = make_float4(0.f,0.f,0.f,0.f);
        #pragma unroll 4
        for (int k = 0; k < 16; k++){
            int n = nbase + k;
            *(float4*)&out[((size_t)b*NSEQ + n)*NSEQ + m] = z;
        }
        return;
    }
    const float4* chp = ((const float4*)g_chp) + (size_t)b*NSEQ;
    float4 q0 = chp[m+0], q1 = chp[m+1], q2 = chp[m+2], q3 = chp[m+3];
    #pragma unroll 2
    for (int k = 0; k < 16; k++){
        int n = nbase + k;
        float4 v = make_float4(0.f,0.f,0.f,0.f);
        if (m0 <= n){
            float4 cn = chp[n];
            float irs = __frcp_rn(g_rs[b*NSEQ + n]);
            float4 cc = *(const float4*)&g_C[((size_t)b*NSEQ + n)*NSEQ + m];
            float f0 = fmaf(cn.x,q0.x, fmaf(cn.y,q0.y, fmaf(cn.z,q0.z, fmaf(cn.w,q0.w, 1.f))));
            float f1 = fmaf(cn.x,q1.x, fmaf(cn.y,q1.y, fmaf(cn.z,q1.z, fmaf(cn.w,q1.w, 1.f))));
            float f2 = fmaf(cn.x,q2.x, fmaf(cn.y,q2.y, fmaf(cn.z,q2.z, fmaf(cn.w,q2.w, 1.f))));
            float f3 = fmaf(cn.x,q3.x, fmaf(cn.y,q3.y, fmaf(cn.z,q3.z, fmaf(cn.w,q3.w, 1.f))));
            v.x = (m+0<=n) ? __expf(cc.x*f0)*irs : 0.f;
            v.y = (m+1<=n) ? __expf(cc.y*f1)*irs : 0.f;
            v.z = (m+2<=n) ? __expf(cc.z*f2)*irs : 0.f;
            v.w = (m+3<=n) ? __expf(cc.w*f3)*irs : 0.f;
        }
        *(float4*)&out[((size_t)b*NSEQ + n)*NSEQ + m] = v;
    }
}

// ---------------- launch ----------------
extern "C" void kernel_launch(void* const* d_in, const int* in_sizes, int n_in,
                              void* d_out, int out_size)
{
    const float* feat = (const float*)d_in[0];
    const float* cosb = (const float*)d_in[1];
    const float* sinb = (const float*)d_in[2];
    // d_in[3] = mask (causal; not needed)
    const float* Wq   = (const float*)d_in[4];
    const float* Wk   = (const float*)d_in[5];
    const float* cw   = (const float*)d_in[6];
    const float* cb   = (const float*)d_in[7];
    const float* ssp  = (const float*)d_in[8];
    const float* cdp  = (const float*)d_in[9];
    float* out = (float*)d_out;

    qk_rope_kernel<<<BN/16, 256>>>(feat, cosb, sinb, Wq, Wk);
    charge0_kernel<<<BN/8, 256>>>(feat, cw, cb);

    const int T = NSEQ/128;
    dim3 g3(T*(T+1)/2, BATCH);
    gemm3_kernel<<<g3, 256>>>();

    dim3 grow(NSEQ/512, NSEQ/64, BATCH);
    dim3 gcol(NSEQ/128, NSEQ/256, BATCH);
    for (int t = 0; t < 4; t++){
        rowsum_kernel<<<grow, 256>>>();
        colsum_kernel<<<gcol, 256>>>();
        chargeupd_kernel<<<BN/256, 256>>>(t, cdp, ssp);
    }
    rowsum_kernel<<<grow, 256>>>();
    dim3 gout(NSEQ/128, NSEQ/128, BATCH);
    output_kernel<<<gout, 256>>>(out);
}

// round 5
// speedup vs baseline: 2.0243x; 1.2931x over previous
#include <cuda_runtime.h>
#include <math.h>

#define NSEQ 4096
#define BATCH 2
#define BN (BATCH*NSEQ)
#define FDIM 512
#define DDIM 64
#define MASKVAL (-12800.0f)
#define SCALE_LOG2E (0.125f*1.4426950408889634f)

// ---------------- scratch (device globals; no allocation allowed) ----------------
__device__ float g_Q[(size_t)BN*DDIM];
__device__ float g_K[(size_t)BN*DDIM];
__device__ float g_C[(size_t)BATCH*NSEQ*NSEQ];   // C' = (QK^T/8)*log2e, above-diag = MASKVAL
__device__ float g_ch[BN];                       // current charge
__device__ float g_chpt[4][BN];                  // transposed packed sqrt(ss)*charge history
__device__ float g_rs[BN];                       // rowsum accumulator
__device__ float g_recv[BN];                     // column sums (received)

__device__ __forceinline__ float sigmoidf_(float x){ return 1.f/(1.f+__expf(-x)); }
__device__ __forceinline__ float ex2_(float x){ float y; asm("ex2.approx.f32 %0, %1;" : "=f"(y) : "f"(x)); return y; }

// ---------------- Q/K projection + RoPE ----------------
__global__ void qk_rope_kernel(const float* __restrict__ feat,
                               const float* __restrict__ cosb,
                               const float* __restrict__ sinb,
                               const float* __restrict__ Wq,
                               const float* __restrict__ Wk)
{
    __shared__ float fs[16][64];
    __shared__ float qs[16][64];
    __shared__ float ks[16][64];
    int tid = threadIdx.x;
    int d = tid & 63, rg = tid >> 6;
    long rowbase = (long)blockIdx.x * 16;
    float accq[4] = {0,0,0,0}, acck[4] = {0,0,0,0};
    for (int f0 = 0; f0 < FDIM; f0 += 64){
        __syncthreads();
        for (int i = tid; i < 16*64; i += 256){
            int r = i >> 6, f = i & 63;
            fs[r][f] = feat[(rowbase + r)*FDIM + f0 + f];
        }
        __syncthreads();
        #pragma unroll 8
        for (int f = 0; f < 64; f++){
            float wq = Wq[(f0+f)*DDIM + d];
            float wk = Wk[(f0+f)*DDIM + d];
            #pragma unroll
            for (int i = 0; i < 4; i++){
                float fv = fs[rg*4+i][f];
                accq[i] = fmaf(fv, wq, accq[i]);
                acck[i] = fmaf(fv, wk, acck[i]);
            }
        }
    }
    __syncthreads();
    #pragma unroll
    for (int i = 0; i < 4; i++){ qs[rg*4+i][d] = accq[i]; ks[rg*4+i][d] = acck[i]; }
    __syncthreads();
    #pragma unroll
    for (int i = 0; i < 4; i++){
        int r = rg*4+i;
        long n = rowbase + r;
        int nn = (int)(n & (NSEQ-1));
        float c = cosb[nn*DDIM+d], s = sinb[nn*DDIM+d];
        float q = qs[r][d], k = ks[r][d];
        float qr = (d < 32) ? -qs[r][d+32] : qs[r][d-32];
        float kr = (d < 32) ? -ks[r][d+32] : ks[r][d-32];
        g_Q[n*DDIM+d] = q*c + qr*s;
        g_K[n*DDIM+d] = k*c + kr*s;
    }
}

// ---------------- initial charge + zero recv/rs/chpt ----------------
__global__ void charge0_kernel(const float* __restrict__ feat,
                               const float* __restrict__ cw,
                               const float* __restrict__ cb)
{
    int warp = threadIdx.x >> 5, lane = threadIdx.x & 31;
    long n = (long)blockIdx.x*8 + warp;
    if (n >= BN) return;
    float sum = 0.f;
    for (int f = lane; f < FDIM; f += 32) sum = fmaf(feat[n*FDIM+f], cw[f], sum);
    #pragma unroll
    for (int o = 16; o > 0; o >>= 1) sum += __shfl_down_sync(0xffffffffu, sum, o);
    if (lane == 0){
        g_ch[n] = sigmoidf_(sum + cb[0]);
        g_recv[n] = 0.f;
        g_rs[n] = 0.f;
        #pragma unroll
        for (int t = 0; t < 4; t++) g_chpt[t][n] = 0.f;
    }
}

// ---------------- C' = QK^T * (log2e/8), lower-tri 128x128 tiles; mask baked ----------------
__global__ void __launch_bounds__(256, 2) gemm3_kernel()
{
    int b = blockIdx.y;
    int kidx = blockIdx.x;
    int ti = (int)((sqrtf(8.f*(float)kidx + 1.f) - 1.f) * 0.5f);
    while ((ti+1)*(ti+2)/2 <= kidx) ti++;
    while (ti*(ti+1)/2 > kidx) ti--;
    int tj = kidx - ti*(ti+1)/2;

    __shared__ float Qs[128][33];
    __shared__ float Ks[128][33];
    const float* Qb = g_Q + ((long)b*NSEQ + (long)ti*128)*DDIM;
    const float* Kb = g_K + ((long)b*NSEQ + (long)tj*128)*DDIM;
    int tid = threadIdx.x;
    int tx = tid & 15, ty = tid >> 4;
    float acc[8][8] = {};
    for (int k0 = 0; k0 < 64; k0 += 32){
        __syncthreads();
        for (int i = tid; i < 128*32; i += 256){
            int r = i >> 5, k = i & 31;
            Qs[r][k] = Qb[r*64 + k0 + k];
            Ks[r][k] = Kb[r*64 + k0 + k];
        }
        __syncthreads();
        #pragma unroll
        for (int kk = 0; kk < 32; kk++){
            float a[8], bb[8];
            #pragma unroll
            for (int i = 0; i < 8; i++) a[i]  = Qs[ty + i*16][kk];
            #pragma unroll
            for (int j = 0; j < 8; j++) bb[j] = Ks[tx + j*16][kk];
            #pragma unroll
            for (int i = 0; i < 8; i++)
                #pragma unroll
                for (int j = 0; j < 8; j++)
                    acc[i][j] = fmaf(a[i], bb[j], acc[i][j]);
        }
    }
    float* Cb = g_C + (size_t)b*NSEQ*NSEQ;
    bool diag = (ti == tj);
    #pragma unroll
    for (int i = 0; i < 8; i++){
        int lrow = ty + i*16;
        long row = (long)ti*128 + lrow;
        #pragma unroll
        for (int j = 0; j < 8; j++){
            int lcol = tx + j*16;
            float v = acc[i][j]*SCALE_LOG2E;
            if (diag && lrow < lcol) v = MASKVAL;
            Cb[row*NSEQ + tj*128 + lcol] = v;
        }
    }
}

// ---------------- rowsum: warp = 8 rows x 512 cols, T active charge comps ----------------
template<int T>
__global__ void __launch_bounds__(256) rowsum_kernel()
{
    int b  = blockIdx.z;
    int m0 = blockIdx.x * 512;
    int n0 = blockIdx.y * 64;
    if (m0 > n0 + 63) return;
    int lane = threadIdx.x & 31, wid = threadIdx.x >> 5;
    int nr0 = n0 + wid*8;
    const float* Cb = g_C + (size_t)b*NSEQ*NSEQ;
    float acc[8] = {0.f,0.f,0.f,0.f,0.f,0.f,0.f,0.f};
    #pragma unroll
    for (int i = 0; i < 4; i++){
        int mchunk = m0 + i*128;
        if (mchunk > nr0 + 7) break;
        int m = mchunk + lane*4;
        float4 q[(T>0)?T:1];
        #pragma unroll
        for (int t = 0; t < T; t++) q[t] = *(const float4*)&g_chpt[t][b*NSEQ + m];
        #pragma unroll
        for (int r = 0; r < 8; r++){
            int n = nr0 + r;
            float4 cc = *(const float4*)&Cb[(size_t)n*NSEQ + m];
            float fx = 1.f, fy = 1.f, fz = 1.f, fw = 1.f;
            #pragma unroll
            for (int t = 0; t < T; t++){
                float cn = g_chpt[t][b*NSEQ + n];
                fx = fmaf(cn, q[t].x, fx);
                fy = fmaf(cn, q[t].y, fy);
                fz = fmaf(cn, q[t].z, fz);
                fw = fmaf(cn, q[t].w, fw);
            }
            float e0 = (T==0) ? ex2_(cc.x) : ex2_(cc.x*fx);
            float e1 = (T==0) ? ex2_(cc.y) : ex2_(cc.y*fy);
            float e2 = (T==0) ? ex2_(cc.z) : ex2_(cc.z*fz);
            float e3 = (T==0) ? ex2_(cc.w) : ex2_(cc.w*fw);
            acc[r] += (e0 + e1) + (e2 + e3);
        }
    }
    #pragma unroll
    for (int r = 0; r < 8; r++){
        float s = acc[r];
        #pragma unroll
        for (int o = 16; o > 0; o >>= 1) s += __shfl_down_sync(0xffffffffu, s, o);
        if (lane == 0 && s != 0.f) atomicAdd(&g_rs[b*NSEQ + nr0 + r], s);
    }
}

// ---------------- colsum (received): block = 128 cols x 256 rows ----------------
template<int T>
__global__ void __launch_bounds__(256) colsum_kernel()
{
    int b  = blockIdx.z;
    int m0 = blockIdx.x * 128;
    int n0 = blockIdx.y * 256;
    if (m0 > n0 + 255) return;
    int tid = threadIdx.x, lane = tid & 31, wid = tid >> 5;
    int m = m0 + lane*4;
    float4 q[(T>0)?T:1];
    #pragma unroll
    for (int t = 0; t < T; t++) q[t] = *(const float4*)&g_chpt[t][b*NSEQ + m];
    float4 acc = make_float4(0.f,0.f,0.f,0.f);
    int nbase = n0 + wid*32;
    #pragma unroll 4
    for (int k = 0; k < 32; k++){
        int n = nbase + k;
        if (m0 > n) continue;
        float irs = __frcp_rn(g_rs[b*NSEQ + n]);
        float4 cc = *(const float4*)&g_C[((size_t)b*NSEQ + n)*NSEQ + m];
        float fx = 1.f, fy = 1.f, fz = 1.f, fw = 1.f;
        #pragma unroll
        for (int t = 0; t < T; t++){
            float cn = g_chpt[t][b*NSEQ + n];
            fx = fmaf(cn, q[t].x, fx);
            fy = fmaf(cn, q[t].y, fy);
            fz = fmaf(cn, q[t].z, fz);
            fw = fmaf(cn, q[t].w, fw);
        }
        acc.x += ((T==0) ? ex2_(cc.x) : ex2_(cc.x*fx))*irs;
        acc.y += ((T==0) ? ex2_(cc.y) : ex2_(cc.y*fy))*irs;
        acc.z += ((T==0) ? ex2_(cc.z) : ex2_(cc.z*fz))*irs;
        acc.w += ((T==0) ? ex2_(cc.w) : ex2_(cc.w*fw))*irs;
    }
    __shared__ float4 s4[256];
    s4[tid] = acc;
    __syncthreads();
    if (tid < 32){
        float4 t = s4[tid];
        #pragma unroll
        for (int r = 1; r < 8; r++){
            float4 o = s4[tid + r*32];
            t.x += o.x; t.y += o.y; t.z += o.z; t.w += o.w;
        }
        float* dst = &g_recv[b*NSEQ + m0 + tid*4];
        atomicAdd(dst+0, t.x);
        atomicAdd(dst+1, t.y);
        atomicAdd(dst+2, t.z);
        atomicAdd(dst+3, t.w);
    }
}

// ---------------- charge update + pack + re-zero recv/rs ----------------
__global__ void chargeupd_kernel(int t, const float* __restrict__ cdp,
                                        const float* __restrict__ ssp)
{
    int i = blockIdx.x*256 + threadIdx.x;
    if (i >= BN) return;
    float cd = *cdp, ss = *ssp;
    float r  = g_recv[i];
    float ch = g_ch[i] * (1.f - cd*sigmoidf_(r - 1.f));
    g_ch[i] = ch;
    g_chpt[t][i] = sqrtf(ss)*ch;
    g_recv[i] = 0.f;
    g_rs[i] = 0.f;
}

// ---------------- tiled output: block = 128 cols x 128 rows ----------------
__global__ void __launch_bounds__(256) output_kernel(float* __restrict__ out)
{
    int b  = blockIdx.z;
    int m0 = blockIdx.x * 128;
    int n0 = blockIdx.y * 128;
    int tid = threadIdx.x, lane = tid & 31, wid = tid >> 5;
    int m = m0 + lane*4;
    int nbase = n0 + wid*16;
    if (m0 > n0 + 127){
        float4 z = make_float4(0.f,0.f,0.f,0.f);
        #pragma unroll 4
        for (int k = 0; k < 16; k++){
            int n = nbase + k;
            *(float4*)&out[((size_t)b*NSEQ + n)*NSEQ + m] = z;
        }
        return;
    }
    float4 q[4];
    #pragma unroll
    for (int t = 0; t < 4; t++) q[t] = *(const float4*)&g_chpt[t][b*NSEQ + m];
    #pragma unroll 2
    for (int k = 0; k < 16; k++){
        int n = nbase + k;
        float4 v = make_float4(0.f,0.f,0.f,0.f);
        if (m0 <= n){
            float irs = __frcp_rn(g_rs[b*NSEQ + n]);
            float4 cc = *(const float4*)&g_C[((size_t)b*NSEQ + n)*NSEQ + m];
            float fx = 1.f, fy = 1.f, fz = 1.f, fw = 1.f;
            #pragma unroll
            for (int t = 0; t < 4; t++){
                float cn = g_chpt[t][b*NSEQ + n];
                fx = fmaf(cn, q[t].x, fx);
                fy = fmaf(cn, q[t].y, fy);
                fz = fmaf(cn, q[t].z, fz);
                fw = fmaf(cn, q[t].w, fw);
            }
            v.x = ex2_(cc.x*fx)*irs;
            v.y = ex2_(cc.y*fy)*irs;
            v.z = ex2_(cc.z*fz)*irs;
            v.w = ex2_(cc.w*fw)*irs;
        }
        *(float4*)&out[((size_t)b*NSEQ + n)*NSEQ + m] = v;
    }
}

// ---------------- launch ----------------
extern "C" void kernel_launch(void* const* d_in, const int* in_sizes, int n_in,
                              void* d_out, int out_size)
{
    const float* feat = (const float*)d_in[0];
    const float* cosb = (const float*)d_in[1];
    const float* sinb = (const float*)d_in[2];
    // d_in[3] = mask (causal; not needed)
    const float* Wq   = (const float*)d_in[4];
    const float* Wk   = (const float*)d_in[5];
    const float* cw   = (const float*)d_in[6];
    const float* cb   = (const float*)d_in[7];
    const float* ssp  = (const float*)d_in[8];
    const float* cdp  = (const float*)d_in[9];
    float* out = (float*)d_out;

    qk_rope_kernel<<<BN/16, 256>>>(feat, cosb, sinb, Wq, Wk);
    charge0_kernel<<<BN/8, 256>>>(feat, cw, cb);

    const int T = NSEQ/128;
    dim3 g3(T*(T+1)/2, BATCH);
    gemm3_kernel<<<g3, 256>>>();

    dim3 grow(NSEQ/512, NSEQ/64, BATCH);
    dim3 gcol(NSEQ/128, NSEQ/256, BATCH);

    rowsum_kernel<0><<<grow, 256>>>();
    colsum_kernel<0><<<gcol, 256>>>();
    chargeupd_kernel<<<BN/256, 256>>>(0, cdp, ssp);

    rowsum_kernel<1><<<grow, 256>>>();
    colsum_kernel<1><<<gcol, 256>>>();
    chargeupd_kernel<<<BN/256, 256>>>(1, cdp, ssp);

    rowsum_kernel<2><<<grow, 256>>>();
    colsum_kernel<2><<<gcol, 256>>>();
    chargeupd_kernel<<<BN/256, 256>>>(2, cdp, ssp);

    rowsum_kernel<3><<<grow, 256>>>();
    colsum_kernel<3><<<gcol, 256>>>();
    chargeupd_kernel<<<BN/256, 256>>>(3, cdp, ssp);

    rowsum_kernel<4><<<grow, 256>>>();
    dim3 gout(NSEQ/128, NSEQ/128, BATCH);
    output_kernel<<<gout, 256>>>(out);
}

// round 8
// speedup vs baseline: 2.2102x; 1.0918x over previous
#include <cuda_runtime.h>
#include <cuda_bf16.h>
#include <cstdint>
#include <math.h>

#define NSEQ 4096
#define BATCH 2
#define BN (BATCH*NSEQ)
#define FDIM 512
#define DDIM 64
#define MASKVAL (-12800.0f)
#define SCALE_LOG2E (0.125f*1.4426950408889634f)
#define SQ 72   // padded bf16 row stride for mma smem tiles

// ---------------- scratch (device globals; no allocation allowed) ----------------
__device__ float g_Q[(size_t)BN*DDIM];
__device__ float g_K[(size_t)BN*DDIM];
__device__ float g_C[(size_t)BATCH*NSEQ*NSEQ];   // C' = (QK^T/8)*log2e, above-diag = MASKVAL in diag tiles
__device__ float g_ch[BN];                       // current charge
__device__ float g_chpt[4][BN];                  // transposed packed sqrt(ss)*charge history
__device__ float g_rs[BN];                       // rowsum accumulator
__device__ float g_recv[BN];                     // column sums (received)

__device__ __forceinline__ float sigmoidf_(float x){ return 1.f/(1.f+__expf(-x)); }
__device__ __forceinline__ float ex2_(float x){ float y; asm("ex2.approx.f32 %0, %1;" : "=f"(y) : "f"(x)); return y; }
__device__ __forceinline__ uint32_t smem_u32_(const void* p){
    uint32_t a;
    asm("{ .reg .u64 t; cvta.to.shared.u64 t, %1; cvt.u32.u64 %0, t; }" : "=r"(a) : "l"(p));
    return a;
}

// ---------------- Q/K projection + RoPE ----------------
__global__ void qk_rope_kernel(const float* __restrict__ feat,
                               const float* __restrict__ cosb,
                               const float* __restrict__ sinb,
                               const float* __restrict__ Wq,
                               const float* __restrict__ Wk)
{
    __shared__ float fs[16][64];
    __shared__ float qs[16][64];
    __shared__ float ks[16][64];
    int tid = threadIdx.x;
    int d = tid & 63, rg = tid >> 6;
    long rowbase = (long)blockIdx.x * 16;
    float accq[4] = {0,0,0,0}, acck[4] = {0,0,0,0};
    for (int f0 = 0; f0 < FDIM; f0 += 64){
        __syncthreads();
        for (int i = tid; i < 16*64; i += 256){
            int r = i >> 6, f = i & 63;
            fs[r][f] = feat[(rowbase + r)*FDIM + f0 + f];
        }
        __syncthreads();
        #pragma unroll 8
        for (int f = 0; f < 64; f++){
            float wq = Wq[(f0+f)*DDIM + d];
            float wk = Wk[(f0+f)*DDIM + d];
            #pragma unroll
            for (int i = 0; i < 4; i++){
                float fv = fs[rg*4+i][f];
                accq[i] = fmaf(fv, wq, accq[i]);
                acck[i] = fmaf(fv, wk, acck[i]);
            }
        }
    }
    __syncthreads();
    #pragma unroll
    for (int i = 0; i < 4; i++){ qs[rg*4+i][d] = accq[i]; ks[rg*4+i][d] = acck[i]; }
    __syncthreads();
    #pragma unroll
    for (int i = 0; i < 4; i++){
        int r = rg*4+i;
        long n = rowbase + r;
        int nn = (int)(n & (NSEQ-1));
        float c = cosb[nn*DDIM+d], s = sinb[nn*DDIM+d];
        float q = qs[r][d], k = ks[r][d];
        float qr = (d < 32) ? -qs[r][d+32] : qs[r][d-32];
        float kr = (d < 32) ? -ks[r][d+32] : ks[r][d-32];
        g_Q[n*DDIM+d] = q*c + qr*s;
        g_K[n*DDIM+d] = k*c + kr*s;
    }
}

// ---------------- initial charge + zero recv/rs/chpt ----------------
__global__ void charge0_kernel(const float* __restrict__ feat,
                               const float* __restrict__ cw,
                               const float* __restrict__ cb)
{
    int warp = threadIdx.x >> 5, lane = threadIdx.x & 31;
    long n = (long)blockIdx.x*8 + warp;
    if (n >= BN) return;
    float sum = 0.f;
    for (int f = lane; f < FDIM; f += 32) sum = fmaf(feat[n*FDIM+f], cw[f], sum);
    #pragma unroll
    for (int o = 16; o > 0; o >>= 1) sum += __shfl_down_sync(0xffffffffu, sum, o);
    if (lane == 0){
        g_ch[n] = sigmoidf_(sum + cb[0]);
        g_recv[n] = 0.f;
        g_rs[n] = 0.f;
        #pragma unroll
        for (int t = 0; t < 4; t++) g_chpt[t][n] = 0.f;
    }
}

// ---------------- gemm via mma.sync bf16 hi/lo: C' = QK^T*(log2e/8), masked ----------------
__global__ void __launch_bounds__(256) gemm_mma_kernel()
{
    extern __shared__ __nv_bfloat16 smb[];
    __nv_bfloat16* Qhi = smb;
    __nv_bfloat16* Qlo = smb + 128*SQ;
    __nv_bfloat16* Khi = smb + 2*128*SQ;
    __nv_bfloat16* Klo = smb + 3*128*SQ;

    int b = blockIdx.y;
    int kidx = blockIdx.x;
    int ti = (int)((sqrtf(8.f*(float)kidx + 1.f) - 1.f) * 0.5f);
    while ((ti+1)*(ti+2)/2 <= kidx) ti++;
    while (ti*(ti+1)/2 > kidx) ti--;
    int tj = kidx - ti*(ti+1)/2;

    const float* Qb = g_Q + ((long)b*NSEQ + (long)ti*128)*DDIM;
    const float* Kb = g_K + ((long)b*NSEQ + (long)tj*128)*DDIM;
    int tid = threadIdx.x;
    for (int i = tid; i < 128*32; i += 256){
        int r = i >> 5, c2 = i & 31;
        float2 q = *(const float2*)&Qb[r*64 + c2*2];
        float2 k = *(const float2*)&Kb[r*64 + c2*2];
        int o = r*SQ + c2*2;
        __nv_bfloat16 qhx = __float2bfloat16_rn(q.x), qhy = __float2bfloat16_rn(q.y);
        __nv_bfloat16 khx = __float2bfloat16_rn(k.x), khy = __float2bfloat16_rn(k.y);
        __nv_bfloat16 qlx = __float2bfloat16_rn(q.x - __bfloat162float(qhx));
        __nv_bfloat16 qly = __float2bfloat16_rn(q.y - __bfloat162float(qhy));
        __nv_bfloat16 klx = __float2bfloat16_rn(k.x - __bfloat162float(khx));
        __nv_bfloat16 kly = __float2bfloat16_rn(k.y - __bfloat162float(khy));
        *(__nv_bfloat162*)&Qhi[o] = __nv_bfloat162(qhx, qhy);
        *(__nv_bfloat162*)&Qlo[o] = __nv_bfloat162(qlx, qly);
        *(__nv_bfloat162*)&Khi[o] = __nv_bfloat162(khx, khy);
        *(__nv_bfloat162*)&Klo[o] = __nv_bfloat162(klx, kly);
    }
    __syncthreads();

    int lane = tid & 31, w = tid >> 5;
    int wm = (w & 1)*64, wn = (w >> 1)*32;

    float c[4][4][4] = {};

    uint32_t qhi_b = smem_u32_(Qhi), qlo_b = smem_u32_(Qlo);
    uint32_t khi_b = smem_u32_(Khi), klo_b = smem_u32_(Klo);

    int ar = lane & 15, ac8 = lane >> 4;       // A: 16 rows, 2 col-blocks
    int br = lane & 7,  bc8 = (lane >> 3) & 1; // B: 8 rows, 2 col-blocks (x2 uses lanes 0-15)

    #pragma unroll
    for (int combo = 0; combo < 3; combo++){
        uint32_t abase = (combo == 2) ? qlo_b : qhi_b;
        uint32_t bbase = (combo == 1) ? klo_b : khi_b;
        #pragma unroll
        for (int k0 = 0; k0 < 64; k0 += 16){
            uint32_t a[4][4], bf[4][2];
            #pragma unroll
            for (int i = 0; i < 4; i++){
                uint32_t addr = abase + (uint32_t)(((wm + i*16 + ar)*SQ + k0 + ac8*8)*2);
                asm volatile("ldmatrix.sync.aligned.m8n8.x4.shared.b16 {%0,%1,%2,%3}, [%4];"
                    : "=r"(a[i][0]), "=r"(a[i][1]), "=r"(a[i][2]), "=r"(a[i][3]) : "r"(addr));
            }
            #pragma unroll
            for (int j = 0; j < 4; j++){
                uint32_t addr = bbase + (uint32_t)(((wn + j*8 + br)*SQ + k0 + bc8*8)*2);
                asm volatile("ldmatrix.sync.aligned.m8n8.x2.shared.b16 {%0,%1}, [%2];"
                    : "=r"(bf[j][0]), "=r"(bf[j][1]) : "r"(addr));
            }
            #pragma unroll
            for (int i = 0; i < 4; i++)
                #pragma unroll
                for (int j = 0; j < 4; j++)
                    asm volatile("mma.sync.aligned.m16n8k16.row.col.f32.bf16.bf16.f32 "
                        "{%0,%1,%2,%3}, {%4,%5,%6,%7}, {%8,%9}, {%0,%1,%2,%3};"
                        : "+f"(c[i][j][0]), "+f"(c[i][j][1]), "+f"(c[i][j][2]), "+f"(c[i][j][3])
                        : "r"(a[i][0]), "r"(a[i][1]), "r"(a[i][2]), "r"(a[i][3]),
                          "r"(bf[j][0]), "r"(bf[j][1]));
        }
    }

    // epilogue: scale, diag mask, direct stores (float2 per frag row)
    float* Cb = g_C + (size_t)b*NSEQ*NSEQ;
    bool diag = (ti == tj);
    int rq = lane >> 2, cq = (lane & 3)*2;
    #pragma unroll
    for (int i = 0; i < 4; i++){
        int lr0 = wm + i*16 + rq;
        #pragma unroll
        for (int j = 0; j < 4; j++){
            int lc = wn + j*8 + cq;
            float2 v0 = make_float2(c[i][j][0]*SCALE_LOG2E, c[i][j][1]*SCALE_LOG2E);
            float2 v1 = make_float2(c[i][j][2]*SCALE_LOG2E, c[i][j][3]*SCALE_LOG2E);
            if (diag){
                if (lr0 < lc)       v0.x = MASKVAL;
                if (lr0 < lc+1)     v0.y = MASKVAL;
                if (lr0+8 < lc)     v1.x = MASKVAL;
                if (lr0+8 < lc+1)   v1.y = MASKVAL;
            }
            size_t row0 = (size_t)(ti*128 + lr0);
            int col = tj*128 + lc;
            *(float2*)&Cb[row0*NSEQ + col] = v0;
            *(float2*)&Cb[(row0+8)*NSEQ + col] = v1;
        }
    }
}

// ---------------- rowsum: warp = 8 rows x 512 cols, T active charge comps ----------------
template<int T>
__global__ void __launch_bounds__(256) rowsum_kernel()
{
    int b  = blockIdx.z;
    int m0 = blockIdx.x * 512;
    int n0 = blockIdx.y * 64;
    if (m0 > n0 + 63) return;
    int lane = threadIdx.x & 31, wid = threadIdx.x >> 5;
    int nr0 = n0 + wid*8;
    const float* Cb = g_C + (size_t)b*NSEQ*NSEQ;
    float acc[8] = {0.f,0.f,0.f,0.f,0.f,0.f,0.f,0.f};
    #pragma unroll
    for (int i = 0; i < 4; i++){
        int mchunk = m0 + i*128;
        if (mchunk > nr0 + 7) break;
        int m = mchunk + lane*4;
        float4 q[(T>0)?T:1];
        #pragma unroll
        for (int t = 0; t < T; t++) q[t] = *(const float4*)&g_chpt[t][b*NSEQ + m];
        #pragma unroll
        for (int r = 0; r < 8; r++){
            int n = nr0 + r;
            float4 cc = *(const float4*)&Cb[(size_t)n*NSEQ + m];
            float fx = 1.f, fy = 1.f, fz = 1.f, fw = 1.f;
            #pragma unroll
            for (int t = 0; t < T; t++){
                float cn = g_chpt[t][b*NSEQ + n];
                fx = fmaf(cn, q[t].x, fx);
                fy = fmaf(cn, q[t].y, fy);
                fz = fmaf(cn, q[t].z, fz);
                fw = fmaf(cn, q[t].w, fw);
            }
            float e0 = (T==0) ? ex2_(cc.x) : ex2_(cc.x*fx);
            float e1 = (T==0) ? ex2_(cc.y) : ex2_(cc.y*fy);
            float e2 = (T==0) ? ex2_(cc.z) : ex2_(cc.z*fz);
            float e3 = (T==0) ? ex2_(cc.w) : ex2_(cc.w*fw);
            acc[r] += (e0 + e1) + (e2 + e3);
        }
    }
    #pragma unroll
    for (int r = 0; r < 8; r++){
        float s = acc[r];
        #pragma unroll
        for (int o = 16; o > 0; o >>= 1) s += __shfl_down_sync(0xffffffffu, s, o);
        if (lane == 0 && s != 0.f) atomicAdd(&g_rs[b*NSEQ + nr0 + r], s);
    }
}

// ---------------- colsum (received): block = 128 cols x 256 rows ----------------
template<int T>
__global__ void __launch_bounds__(256) colsum_kernel()
{
    int b  = blockIdx.z;
    int m0 = blockIdx.x * 128;
    int n0 = blockIdx.y * 256;
    if (m0 > n0 + 255) return;
    int tid = threadIdx.x, lane = tid & 31, wid = tid >> 5;
    int m = m0 + lane*4;
    float4 q[(T>0)?T:1];
    #pragma unroll
    for (int t = 0; t < T; t++) q[t] = *(const float4*)&g_chpt[t][b*NSEQ + m];
    float4 acc = make_float4(0.f,0.f,0.f,0.f);
    int nbase = n0 + wid*32;
    #pragma unroll 4
    for (int k = 0; k < 32; k++){
        int n = nbase + k;
        if (m0 > n) continue;
        float irs = __frcp_rn(g_rs[b*NSEQ + n]);
        float4 cc = *(const float4*)&g_C[((size_t)b*NSEQ + n)*NSEQ + m];
        float fx = 1.f, fy = 1.f, fz = 1.f, fw = 1.f;
        #pragma unroll
        for (int t = 0; t < T; t++){
            float cn = g_chpt[t][b*NSEQ + n];
            fx = fmaf(cn, q[t].x, fx);
            fy = fmaf(cn, q[t].y, fy);
            fz = fmaf(cn, q[t].z, fz);
            fw = fmaf(cn, q[t].w, fw);
        }
        acc.x += ((T==0) ? ex2_(cc.x) : ex2_(cc.x*fx))*irs;
        acc.y += ((T==0) ? ex2_(cc.y) : ex2_(cc.y*fy))*irs;
        acc.z += ((T==0) ? ex2_(cc.z) : ex2_(cc.z*fz))*irs;
        acc.w += ((T==0) ? ex2_(cc.w) : ex2_(cc.w*fw))*irs;
    }
    __shared__ float4 s4[256];
    s4[tid] = acc;
    __syncthreads();
    if (tid < 32){
        float4 t = s4[tid];
        #pragma unroll
        for (int r = 1; r < 8; r++){
            float4 o = s4[tid + r*32];
            t.x += o.x; t.y += o.y; t.z += o.z; t.w += o.w;
        }
        float* dst = &g_recv[b*NSEQ + m0 + tid*4];
        atomicAdd(dst+0, t.x);
        atomicAdd(dst+1, t.y);
        atomicAdd(dst+2, t.z);
        atomicAdd(dst+3, t.w);
    }
}

// ---------------- charge update + pack + re-zero recv/rs ----------------
__global__ void chargeupd_kernel(int t, const float* __restrict__ cdp,
                                        const float* __restrict__ ssp)
{
    int i = blockIdx.x*256 + threadIdx.x;
    if (i >= BN) return;
    float cd = *cdp, ss = *ssp;
    float r  = g_recv[i];
    float ch = g_ch[i] * (1.f - cd*sigmoidf_(r - 1.f));
    g_ch[i] = ch;
    g_chpt[t][i] = sqrtf(ss)*ch;
    g_recv[i] = 0.f;
    g_rs[i] = 0.f;
}

// ---------------- fused final: row-strip rowsum + normalized write ----------------
__global__ void __launch_bounds__(256) final_fused_kernel(float* __restrict__ out)
{
    __shared__ float P[NSEQ];
    __shared__ float red[9];
    int blk = blockIdx.x;
    int b = blk & 1;
    int n = (NSEQ-1) - (blk >> 1);           // long rows first
    const float* Crow = g_C + ((size_t)b*NSEQ + n)*NSEQ;
    int tid = threadIdx.x, lane = tid & 31, wid = tid >> 5;
    int L = ((n >> 7) + 1) << 7;             // length rounded up to 128 (mask covers rest)
    float cn0 = g_chpt[0][b*NSEQ+n];
    float cn1 = g_chpt[1][b*NSEQ+n];
    float cn2 = g_chpt[2][b*NSEQ+n];
    float cn3 = g_chpt[3][b*NSEQ+n];
    float sum = 0.f;
    for (int i = tid; i < (L >> 2); i += 256){
        float4 cc = ((const float4*)Crow)[i];
        int m = b*NSEQ + i*4;
        float4 t0 = *(const float4*)&g_chpt[0][m];
        float4 t1 = *(const float4*)&g_chpt[1][m];
        float4 t2 = *(const float4*)&g_chpt[2][m];
        float4 t3 = *(const float4*)&g_chpt[3][m];
        float fx = fmaf(cn0,t0.x, fmaf(cn1,t1.x, fmaf(cn2,t2.x, fmaf(cn3,t3.x, 1.f))));
        float fy = fmaf(cn0,t0.y, fmaf(cn1,t1.y, fmaf(cn2,t2.y, fmaf(cn3,t3.y, 1.f))));
        float fz = fmaf(cn0,t0.z, fmaf(cn1,t1.z, fmaf(cn2,t2.z, fmaf(cn3,t3.z, 1.f))));
        float fw = fmaf(cn0,t0.w, fmaf(cn1,t1.w, fmaf(cn2,t2.w, fmaf(cn3,t3.w, 1.f))));
        float p0 = ex2_(cc.x*fx), p1 = ex2_(cc.y*fy);
        float p2 = ex2_(cc.z*fz), p3 = ex2_(cc.w*fw);
        *(float4*)&P[i*4] = make_float4(p0,p1,p2,p3);
        sum += (p0 + p1) + (p2 + p3);
    }
    #pragma unroll
    for (int o = 16; o > 0; o >>= 1) sum += __shfl_down_sync(0xffffffffu, sum, o);
    if (lane == 0) red[wid] = sum;
    __syncthreads();
    if (tid == 0){
        float s = 0.f;
        #pragma unroll
        for (int w = 0; w < 8; w++) s += red[w];
        red[8] = 1.f / s;
    }
    __syncthreads();
    float irs = red[8];
    float* orow = out + ((size_t)b*NSEQ + n)*NSEQ;
    int L4 = L >> 2;
    for (int i = tid; i < NSEQ/4; i += 256){
        float4 v = make_float4(0.f,0.f,0.f,0.f);
        if (i < L4){
            float4 p = *(float4*)&P[i*4];
            v = make_float4(p.x*irs, p.y*irs, p.z*irs, p.w*irs);
        }
        *(float4*)&orow[i*4] = v;
    }
}

// ---------------- launch ----------------
extern "C" void kernel_launch(void* const* d_in, const int* in_sizes, int n_in,
                              void* d_out, int out_size)
{
    const float* feat = (const float*)d_in[0];
    const float* cosb = (const float*)d_in[1];
    const float* sinb = (const float*)d_in[2];
    // d_in[3] = mask (causal; not needed)
    const float* Wq   = (const float*)d_in[4];
    const float* Wk   = (const float*)d_in[5];
    const float* cw   = (const float*)d_in[6];
    const float* cb   = (const float*)d_in[7];
    const float* ssp  = (const float*)d_in[8];
    const float* cdp  = (const float*)d_in[9];
    float* out = (float*)d_out;

    const int GSMEM = 4*128*SQ*2;   // 73728 bytes
    static int smem_set = 0;
    if (!smem_set){
        cudaFuncSetAttribute(gemm_mma_kernel, cudaFuncAttributeMaxDynamicSharedMemorySize, GSMEM);
        smem_set = 1;
    }

    qk_rope_kernel<<<BN/16, 256>>>(feat, cosb, sinb, Wq, Wk);
    charge0_kernel<<<BN/8, 256>>>(feat, cw, cb);

    const int T = NSEQ/128;
    dim3 g3(T*(T+1)/2, BATCH);
    gemm_mma_kernel<<<g3, 256, GSMEM>>>();

    dim3 grow(NSEQ/512, NSEQ/64, BATCH);
    dim3 gcol(NSEQ/128, NSEQ/256, BATCH);

    rowsum_kernel<0><<<grow, 256>>>();
    colsum_kernel<0><<<gcol, 256>>>();
    chargeupd_kernel<<<BN/256, 256>>>(0, cdp, ssp);

    rowsum_kernel<1><<<grow, 256>>>();
    colsum_kernel<1><<<gcol, 256>>>();
    chargeupd_kernel<<<BN/256, 256>>>(1, cdp, ssp);

    rowsum_kernel<2><<<grow, 256>>>();
    colsum_kernel<2><<<gcol, 256>>>();
    chargeupd_kernel<<<BN/256, 256>>>(2, cdp, ssp);

    rowsum_kernel<3><<<grow, 256>>>();
    colsum_kernel<3><<<gcol, 256>>>();
    chargeupd_kernel<<<BN/256, 256>>>(3, cdp, ssp);

    final_fused_kernel<<<BN, 256>>>(out);
}